// round 1
// baseline (speedup 1.0000x reference)
#include <cuda_runtime.h>
#include <math.h>

// Problem constants (fixed dataset)
#define B_   16384
#define NF_  50
#define KE_  16      // embedding dim
#define D_   800     // NF_*KE_
#define H_   400     // hidden

// Scratch (static device globals — no allocation in kernel_launch)
__device__ float g_X [B_ * D_];   // gathered embeddings, fp32 [B, 800]
__device__ float g_H0[B_ * H_];   // relu(X@W0+b0)
__device__ float g_H1[B_ * H_];   // relu(H0@W1+b1)
__device__ float g_ZP[B_];        // first + second (+bias)

// ---------------------------------------------------------------------------
// Kernel 1: fused gather + first-order + FM second-order + X materialization.
// One CTA (256 threads) per sample. 800 embedding elements per sample.
// stride 256 keeps (i & 15) == (tid & 15), so each thread accumulates a fixed k.
// ---------------------------------------------------------------------------
__global__ __launch_bounds__(256) void gather_fm_kernel(
    const int*   __restrict__ feats,
    const float* __restrict__ values,
    const float* __restrict__ weights,
    const float* __restrict__ embedding,
    const float* __restrict__ bias)
{
    const int b   = blockIdx.x;
    const int tid = threadIdx.x;
    const int base = b * NF_;

    __shared__ float s1s[KE_];
    __shared__ float s2s[KE_];
    __shared__ float fsum;

    if (tid < KE_) { s1s[tid] = 0.f; s2s[tid] = 0.f; }
    if (tid == KE_) fsum = 0.f;
    __syncthreads();

    float a1 = 0.f, a2 = 0.f, fw = 0.f;
    const int myk = tid & 15;

    for (int i = tid; i < NF_ * KE_; i += 256) {
        const int f = i >> 4;
        const int feat = feats[base + f];
        const float v = values[base + f];
        const float e = embedding[(size_t)feat * KE_ + (i & 15)];
        g_X[(size_t)b * D_ + i] = e;
        const float ev = e * v;
        a1 += ev;
        a2 += ev * ev;
        if ((i & 15) == 0) fw += weights[feat] * v;
    }
    atomicAdd(&s1s[myk], a1);
    atomicAdd(&s2s[myk], a2);
    if ((tid & 15) == 0) atomicAdd(&fsum, fw);
    __syncthreads();

    if (tid == 0) {
        float sec = 0.f;
        #pragma unroll
        for (int k = 0; k < KE_; k++) sec += s1s[k] * s1s[k] - s2s[k];
        g_ZP[b] = fsum + bias[0] + 0.5f * sec;
    }
}

// ---------------------------------------------------------------------------
// Kernel 2/3: tiled fp32 GEMM, C = relu(A[M,K] @ B[K,N] + bias_scalar).
// 64x64 block tile, 256 threads, 4x4 micro-tile, BK=16. N may be ragged.
// ---------------------------------------------------------------------------
__global__ __launch_bounds__(256) void gemm_bias_relu(
    const float* __restrict__ A,
    const float* __restrict__ Bw,
    const float* __restrict__ biasp,
    float*       __restrict__ C,
    int M, int N, int K)
{
    __shared__ float As[16][65];   // [k][m], padded to dodge STS conflicts
    __shared__ float Bs[16][64];   // [k][n]

    const int tid = threadIdx.x;
    const int tx  = tid & 15;      // n direction
    const int ty  = tid >> 4;      // m direction
    const int row0 = blockIdx.y * 64;
    const int col0 = blockIdx.x * 64;

    float acc[4][4];
    #pragma unroll
    for (int i = 0; i < 4; i++)
        #pragma unroll
        for (int j = 0; j < 4; j++) acc[i][j] = 0.f;

    const int arow = tid >> 2;           // 0..63
    const int ak   = (tid & 3) << 2;     // 0,4,8,12
    const int bk   = tid >> 4;           // 0..15
    const int bn   = (tid & 15) << 2;    // 0..60

    for (int k0 = 0; k0 < K; k0 += 16) {
        // A tile: fully in-range (M % 64 == 0, K % 16 == 0), vectorized
        const float4 av = *reinterpret_cast<const float4*>(
            &A[(size_t)(row0 + arow) * K + k0 + ak]);
        As[ak + 0][arow] = av.x;
        As[ak + 1][arow] = av.y;
        As[ak + 2][arow] = av.z;
        As[ak + 3][arow] = av.w;

        // B tile: guard ragged N edge
        const float* brow = &Bw[(size_t)(k0 + bk) * N];
        #pragma unroll
        for (int j = 0; j < 4; j++) {
            const int c = col0 + bn + j;
            Bs[bk][bn + j] = (c < N) ? brow[c] : 0.f;
        }
        __syncthreads();

        #pragma unroll
        for (int kk = 0; kk < 16; kk++) {
            float a[4], bb[4];
            #pragma unroll
            for (int i = 0; i < 4; i++) a[i] = As[kk][ty * 4 + i];
            #pragma unroll
            for (int j = 0; j < 4; j++) bb[j] = Bs[kk][tx * 4 + j];
            #pragma unroll
            for (int i = 0; i < 4; i++)
                #pragma unroll
                for (int j = 0; j < 4; j++)
                    acc[i][j] = fmaf(a[i], bb[j], acc[i][j]);
        }
        __syncthreads();
    }

    const float bv = *biasp;
    #pragma unroll
    for (int i = 0; i < 4; i++) {
        const int r = row0 + ty * 4 + i;
        #pragma unroll
        for (int j = 0; j < 4; j++) {
            const int c = col0 + tx * 4 + j;
            if (c < N) C[(size_t)r * N + c] = fmaxf(acc[i][j] + bv, 0.f);
        }
    }
}

// ---------------------------------------------------------------------------
// Kernel 4: per-sample GEMV (H1[b,:] . W2) + b2, relu, + FM partial, sigmoid.
// One warp per sample.
// ---------------------------------------------------------------------------
__global__ __launch_bounds__(256) void final_kernel(
    const float* __restrict__ W2,
    const float* __restrict__ b2,
    float*       __restrict__ out)
{
    const int gw   = (blockIdx.x * blockDim.x + threadIdx.x) >> 5;
    const int lane = threadIdx.x & 31;
    if (gw >= B_) return;

    float s = 0.f;
    const float* h = &g_H1[(size_t)gw * H_];
    for (int j = lane; j < H_; j += 32) s += h[j] * W2[j];
    #pragma unroll
    for (int o = 16; o; o >>= 1) s += __shfl_xor_sync(0xffffffffu, s, o);

    if (lane == 0) {
        const float hi = fmaxf(s + b2[0], 0.f);
        const float z  = g_ZP[gw] + hi;
        out[gw] = 1.f / (1.f + expf(-z));
    }
}

// ---------------------------------------------------------------------------
extern "C" void kernel_launch(void* const* d_in, const int* in_sizes, int n_in,
                              void* d_out, int out_size)
{
    const int*   feats   = (const int*)  d_in[1];
    const float* values  = (const float*)d_in[2];
    const float* bias    = (const float*)d_in[3];
    const float* weights = (const float*)d_in[4];
    const float* emb     = (const float*)d_in[5];
    const float* W0      = (const float*)d_in[6];
    const float* b0      = (const float*)d_in[7];
    const float* W1      = (const float*)d_in[8];
    const float* b1      = (const float*)d_in[9];
    const float* W2      = (const float*)d_in[10];
    const float* b2      = (const float*)d_in[11];
    float* out = (float*)d_out;

    float *X, *H0, *H1;
    cudaGetSymbolAddress((void**)&X,  g_X);
    cudaGetSymbolAddress((void**)&H0, g_H0);
    cudaGetSymbolAddress((void**)&H1, g_H1);

    // 1) gather + FM + X
    gather_fm_kernel<<<B_, 256>>>(feats, values, weights, emb, bias);

    // 2) H0 = relu(X @ W0 + b0)   [16384,800] x [800,400]
    {
        dim3 grid((H_ + 63) / 64, B_ / 64);
        gemm_bias_relu<<<grid, 256>>>(X, W0, b0, H0, B_, H_, D_);
    }
    // 3) H1 = relu(H0 @ W1 + b1)  [16384,400] x [400,400]
    {
        dim3 grid((H_ + 63) / 64, B_ / 64);
        gemm_bias_relu<<<grid, 256>>>(H0, W1, b1, H1, B_, H_, H_);
    }
    // 4) out = sigmoid(ZP + relu(H1 @ W2 + b2))
    {
        const int warps_per_block = 8;
        const int blocks = (B_ + warps_per_block - 1) / warps_per_block;
        final_kernel<<<blocks, warps_per_block * 32>>>(W2, b2, out);
    }
}

// round 2
// speedup vs baseline: 1.6842x; 1.6842x over previous
#include <cuda_runtime.h>
#include <math.h>
#include <stdint.h>

// Problem constants (fixed dataset)
#define B_   16384
#define NF_  50
#define KE_  16      // embedding dim
#define D_   800     // NF_*KE_
#define H_   400     // hidden

// Scratch (static device globals — no allocation in kernel_launch)
__device__ float g_X [B_ * D_];   // gathered embeddings, fp32 [B, 800]
__device__ float g_H0[B_ * H_];   // relu(X@W0+b0)
__device__ float g_H1[B_ * H_];   // relu(H0@W1+b1)
__device__ float g_ZP[B_];        // first + second (+bias)

// ---------------------------------------------------------------------------
// Kernel 1: fused gather + first-order + FM second-order + X materialization.
// ---------------------------------------------------------------------------
__global__ __launch_bounds__(256) void gather_fm_kernel(
    const int*   __restrict__ feats,
    const float* __restrict__ values,
    const float* __restrict__ weights,
    const float* __restrict__ embedding,
    const float* __restrict__ bias)
{
    const int b   = blockIdx.x;
    const int tid = threadIdx.x;
    const int base = b * NF_;

    __shared__ float s1s[KE_];
    __shared__ float s2s[KE_];
    __shared__ float fsum;

    if (tid < KE_) { s1s[tid] = 0.f; s2s[tid] = 0.f; }
    if (tid == KE_) fsum = 0.f;
    __syncthreads();

    float a1 = 0.f, a2 = 0.f, fw = 0.f;
    const int myk = tid & 15;

    for (int i = tid; i < NF_ * KE_; i += 256) {
        const int f = i >> 4;
        const int feat = feats[base + f];
        const float v = values[base + f];
        const float e = embedding[(size_t)feat * KE_ + (i & 15)];
        g_X[(size_t)b * D_ + i] = e;
        const float ev = e * v;
        a1 += ev;
        a2 += ev * ev;
        if ((i & 15) == 0) fw += weights[feat] * v;
    }
    atomicAdd(&s1s[myk], a1);
    atomicAdd(&s2s[myk], a2);
    if ((tid & 15) == 0) atomicAdd(&fsum, fw);
    __syncthreads();

    if (tid == 0) {
        float sec = 0.f;
        #pragma unroll
        for (int k = 0; k < KE_; k++) sec += s1s[k] * s1s[k] - s2s[k];
        g_ZP[b] = fsum + bias[0] + 0.5f * sec;
    }
}

// ---------------------------------------------------------------------------
// 3xTF32 tensor-core GEMM: C = relu(A[M,K] @ B[K,N] + bias_scalar)
// CTA tile 128x64, BK=16, 256 threads (8 warps: 4 along M x 2 along N),
// warp tile 32x32 via m16n8k8 tf32 mma (2 m-tiles x 4 n-tiles).
// A split into tf32 hi/lo on the fly; 3 MMAs per tile-pair for ~1e-5 accuracy.
// ---------------------------------------------------------------------------
#define BM 128
#define BN 64
#define BK 16
#define ASTR 20   // A smem stride [m][k] — conflict-free frag reads
#define BSTR 72   // B smem stride [k][n] — conflict-free frag reads

__device__ __forceinline__ uint32_t f2tf32(float x) {
    uint32_t r; asm("cvt.rna.tf32.f32 %0, %1;" : "=r"(r) : "f"(x)); return r;
}

__device__ __forceinline__ void mma8(float* c, const uint32_t* a, const uint32_t* b) {
    asm volatile(
        "mma.sync.aligned.m16n8k8.row.col.f32.tf32.tf32.f32 "
        "{%0,%1,%2,%3}, {%4,%5,%6,%7}, {%8,%9}, {%0,%1,%2,%3};"
        : "+f"(c[0]), "+f"(c[1]), "+f"(c[2]), "+f"(c[3])
        : "r"(a[0]), "r"(a[1]), "r"(a[2]), "r"(a[3]), "r"(b[0]), "r"(b[1]));
}

__global__ __launch_bounds__(256) void gemm_tf32_bias_relu(
    const float* __restrict__ A,
    const float* __restrict__ Bw,
    const float* __restrict__ biasp,
    float*       __restrict__ C,
    int M, int N, int K)
{
    __shared__ uint32_t Ahi[BM * ASTR];
    __shared__ uint32_t Alo[BM * ASTR];
    __shared__ uint32_t Bhi[BK * BSTR];
    __shared__ uint32_t Blo[BK * BSTR];

    const int tid  = threadIdx.x;
    const int lane = tid & 31;
    const int w    = tid >> 5;
    const int wm   = (w >> 1) << 5;   // warp M offset within CTA tile
    const int wn   = (w & 1) << 5;    // warp N offset
    const int grp  = lane >> 2;       // groupID
    const int thg  = lane & 3;        // thread-in-group
    const int row0 = blockIdx.y * BM;
    const int col0 = blockIdx.x * BN;

    float acc[2][4][4];
    #pragma unroll
    for (int i = 0; i < 2; i++)
        #pragma unroll
        for (int j = 0; j < 4; j++)
            #pragma unroll
            for (int q = 0; q < 4; q++) acc[i][j][q] = 0.f;

    for (int k0 = 0; k0 < K; k0 += BK) {
        if (k0) __syncthreads();

        // --- A tile: 128x16 = 512 float4 vectors over 256 threads (2 each)
        #pragma unroll
        for (int r = 0; r < 2; r++) {
            const int v  = tid + r * 256;
            const int m  = v >> 2;
            const int k4 = (v & 3) << 2;
            const float4 av = *reinterpret_cast<const float4*>(
                &A[(size_t)(row0 + m) * K + k0 + k4]);
            uint4 hv, lv;
            hv.x = f2tf32(av.x); lv.x = f2tf32(av.x - __uint_as_float(hv.x));
            hv.y = f2tf32(av.y); lv.y = f2tf32(av.y - __uint_as_float(hv.y));
            hv.z = f2tf32(av.z); lv.z = f2tf32(av.z - __uint_as_float(hv.z));
            hv.w = f2tf32(av.w); lv.w = f2tf32(av.w - __uint_as_float(hv.w));
            *reinterpret_cast<uint4*>(&Ahi[m * ASTR + k4]) = hv;
            *reinterpret_cast<uint4*>(&Alo[m * ASTR + k4]) = lv;
        }
        // --- B tile: 16x64 = 256 float4 vectors (1 each), ragged-N guarded
        {
            const int kr = tid >> 4;
            const int n4 = (tid & 15) << 2;
            float4 bv = make_float4(0.f, 0.f, 0.f, 0.f);
            if (col0 + n4 < N)
                bv = *reinterpret_cast<const float4*>(
                    &Bw[(size_t)(k0 + kr) * N + col0 + n4]);
            uint4 hv, lv;
            hv.x = f2tf32(bv.x); lv.x = f2tf32(bv.x - __uint_as_float(hv.x));
            hv.y = f2tf32(bv.y); lv.y = f2tf32(bv.y - __uint_as_float(hv.y));
            hv.z = f2tf32(bv.z); lv.z = f2tf32(bv.z - __uint_as_float(hv.z));
            hv.w = f2tf32(bv.w); lv.w = f2tf32(bv.w - __uint_as_float(hv.w));
            *reinterpret_cast<uint4*>(&Bhi[kr * BSTR + n4]) = hv;
            *reinterpret_cast<uint4*>(&Blo[kr * BSTR + n4]) = lv;
        }
        __syncthreads();

        #pragma unroll
        for (int kk = 0; kk < BK; kk += 8) {
            uint32_t ah[2][4], al[2][4], bh[4][2], bl[4][2];
            #pragma unroll
            for (int i = 0; i < 2; i++) {
                const int r0 = (wm + i * 16 + grp) * ASTR + kk + thg;
                const int r1 = r0 + 8 * ASTR;
                ah[i][0] = Ahi[r0];     ah[i][1] = Ahi[r1];
                ah[i][2] = Ahi[r0 + 4]; ah[i][3] = Ahi[r1 + 4];
                al[i][0] = Alo[r0];     al[i][1] = Alo[r1];
                al[i][2] = Alo[r0 + 4]; al[i][3] = Alo[r1 + 4];
            }
            #pragma unroll
            for (int j = 0; j < 4; j++) {
                const int c0 = (kk + thg) * BSTR + wn + j * 8 + grp;
                bh[j][0] = Bhi[c0]; bh[j][1] = Bhi[c0 + 4 * BSTR];
                bl[j][0] = Blo[c0]; bl[j][1] = Blo[c0 + 4 * BSTR];
            }
            #pragma unroll
            for (int i = 0; i < 2; i++)
                #pragma unroll
                for (int j = 0; j < 4; j++) {
                    mma8(acc[i][j], ah[i], bh[j]);
                    mma8(acc[i][j], al[i], bh[j]);
                    mma8(acc[i][j], ah[i], bl[j]);
                }
        }
    }

    // --- epilogue: scalar bias + relu, write C with ragged-N guard
    const float bv = *biasp;
    #pragma unroll
    for (int i = 0; i < 2; i++) {
        const int r = row0 + wm + i * 16 + grp;
        #pragma unroll
        for (int j = 0; j < 4; j++) {
            const int c = col0 + wn + j * 8 + (thg << 1);
            if (c < N) {
                C[(size_t)r * N + c]           = fmaxf(acc[i][j][0] + bv, 0.f);
                C[(size_t)r * N + c + 1]       = fmaxf(acc[i][j][1] + bv, 0.f);
                C[(size_t)(r + 8) * N + c]     = fmaxf(acc[i][j][2] + bv, 0.f);
                C[(size_t)(r + 8) * N + c + 1] = fmaxf(acc[i][j][3] + bv, 0.f);
            }
        }
    }
}

// ---------------------------------------------------------------------------
// Kernel 4: per-sample GEMV (H1[b,:] . W2) + b2, relu, + FM partial, sigmoid.
// One warp per sample, float4 loads.
// ---------------------------------------------------------------------------
__global__ __launch_bounds__(256) void final_kernel(
    const float* __restrict__ W2,
    const float* __restrict__ b2,
    float*       __restrict__ out)
{
    const int gw   = (blockIdx.x * blockDim.x + threadIdx.x) >> 5;
    const int lane = threadIdx.x & 31;
    if (gw >= B_) return;

    float s = 0.f;
    const float* h = &g_H1[(size_t)gw * H_];
    for (int j = lane * 4; j < H_; j += 128) {
        const float4 hv = *reinterpret_cast<const float4*>(&h[j]);
        const float4 wv = *reinterpret_cast<const float4*>(&W2[j]);
        s += hv.x * wv.x + hv.y * wv.y + hv.z * wv.z + hv.w * wv.w;
    }
    #pragma unroll
    for (int o = 16; o; o >>= 1) s += __shfl_xor_sync(0xffffffffu, s, o);

    if (lane == 0) {
        const float hi = fmaxf(s + b2[0], 0.f);
        const float z  = g_ZP[gw] + hi;
        out[gw] = 1.f / (1.f + expf(-z));
    }
}

// ---------------------------------------------------------------------------
extern "C" void kernel_launch(void* const* d_in, const int* in_sizes, int n_in,
                              void* d_out, int out_size)
{
    const int*   feats   = (const int*)  d_in[1];
    const float* values  = (const float*)d_in[2];
    const float* bias    = (const float*)d_in[3];
    const float* weights = (const float*)d_in[4];
    const float* emb     = (const float*)d_in[5];
    const float* W0      = (const float*)d_in[6];
    const float* b0      = (const float*)d_in[7];
    const float* W1      = (const float*)d_in[8];
    const float* b1      = (const float*)d_in[9];
    const float* W2      = (const float*)d_in[10];
    const float* b2      = (const float*)d_in[11];
    float* out = (float*)d_out;

    float *X, *H0, *H1;
    cudaGetSymbolAddress((void**)&X,  g_X);
    cudaGetSymbolAddress((void**)&H0, g_H0);
    cudaGetSymbolAddress((void**)&H1, g_H1);

    // 1) gather + FM + X
    gather_fm_kernel<<<B_, 256>>>(feats, values, weights, emb, bias);

    // 2) H0 = relu(X @ W0 + b0)   [16384,800] x [800,400]
    {
        dim3 grid((H_ + BN - 1) / BN, B_ / BM);
        gemm_tf32_bias_relu<<<grid, 256>>>(X, W0, b0, H0, B_, H_, D_);
    }
    // 3) H1 = relu(H0 @ W1 + b1)  [16384,400] x [400,400]
    {
        dim3 grid((H_ + BN - 1) / BN, B_ / BM);
        gemm_tf32_bias_relu<<<grid, 256>>>(H0, W1, b1, H1, B_, H_, H_);
    }
    // 4) out = sigmoid(ZP + relu(H1 @ W2 + b2))
    {
        const int warps_per_block = 8;
        const int blocks = (B_ + warps_per_block - 1) / warps_per_block;
        final_kernel<<<blocks, warps_per_block * 32>>>(W2, b2, out);
    }
}

// round 4
// speedup vs baseline: 2.5691x; 1.5254x over previous
#include <cuda_runtime.h>
#include <cuda_bf16.h>
#include <math.h>
#include <stdint.h>

// ---------------- problem constants ----------------
#define B_   16384
#define NF_  50
#define KE_  16
#define D_   800     // NF_*KE_
#define H_   400
#define KP1  832     // padded K for GEMM1 (26 * 32)
#define KP2  448     // padded K for GEMM2 (14 * 32)
#define NP_  448     // padded N (= 7 * 64)
#define TM   128
#define TN   64
#define BKC  32

// ---------------- scratch globals ----------------
__device__ __nv_bfloat16 g_Xhi [B_ * KP1];
__device__ __nv_bfloat16 g_Xlo [B_ * KP1];
__device__ __nv_bfloat16 g_W0hi[NP_ * KP1];   // W0^T hi  [448][832], rows>=400 zero
__device__ __nv_bfloat16 g_W0lo[NP_ * KP1];
__device__ __nv_bfloat16 g_W1hi[NP_ * KP2];   // W1^T hi  [448][448]
__device__ __nv_bfloat16 g_W1lo[NP_ * KP2];
__device__ __nv_bfloat16 g_H0hi[B_ * KP2];    // cols>=400 zeroed by GEMM1 epilogue
__device__ __nv_bfloat16 g_H0lo[B_ * KP2];
__device__ float g_H1[B_ * H_];
__device__ float g_ZP[B_];

// ---------------- PTX helpers ----------------
__device__ __forceinline__ uint32_t smem_u32(const void* p) {
    uint32_t a;
    asm("{ .reg .u64 t; cvta.to.shared.u64 t, %1; cvt.u32.u64 %0, t; }"
        : "=r"(a) : "l"(p));
    return a;
}

#define CP16(dst, src) \
    asm volatile("cp.async.cg.shared.global [%0], [%1], 16;" \
                 :: "r"(dst), "l"(src) : "memory")
#define CP_COMMIT() asm volatile("cp.async.commit_group;" ::: "memory")
#define CP_WAIT(n)  asm volatile("cp.async.wait_group %0;" :: "n"(n) : "memory")

#define LDSM4(r, addr) \
    asm volatile("ldmatrix.sync.aligned.m8n8.x4.shared.b16 {%0,%1,%2,%3}, [%4];" \
        : "=r"((r)[0]), "=r"((r)[1]), "=r"((r)[2]), "=r"((r)[3]) : "r"(addr))

__device__ __forceinline__ void mma16(float* c, const uint32_t* a,
                                      uint32_t b0, uint32_t b1) {
    asm volatile(
        "mma.sync.aligned.m16n8k16.row.col.f32.bf16.bf16.f32 "
        "{%0,%1,%2,%3}, {%4,%5,%6,%7}, {%8,%9}, {%0,%1,%2,%3};"
        : "+f"(c[0]), "+f"(c[1]), "+f"(c[2]), "+f"(c[3])
        : "r"(a[0]), "r"(a[1]), "r"(a[2]), "r"(a[3]), "r"(b0), "r"(b1));
}

__device__ __forceinline__ __nv_bfloat16 bhi(float x) { return __float2bfloat16(x); }

// ---------------------------------------------------------------------------
// Kernel A: transpose+split  W[K][N] fp32 -> T{hi,lo}[NP][KP] bf16 (zero pad)
// ---------------------------------------------------------------------------
__global__ __launch_bounds__(256) void transpose_split(
    const float* __restrict__ W, __nv_bfloat16* __restrict__ Thi,
    __nv_bfloat16* __restrict__ Tlo, int K, int N, int KP, int NP)
{
    __shared__ float t[32][33];
    const int kt = blockIdx.x * 32;
    const int nt = blockIdx.y * 32;
    const int tx = threadIdx.x & 31;
    const int ty = threadIdx.x >> 5;   // 0..7

    #pragma unroll
    for (int i = 0; i < 4; i++) {
        const int k = kt + ty + i * 8;
        float v = 0.f;
        if (k < K && nt + tx < N) v = W[(size_t)k * N + nt + tx];
        t[ty + i * 8][tx] = v;
    }
    __syncthreads();
    #pragma unroll
    for (int i = 0; i < 4; i++) {
        const int n = nt + ty + i * 8;
        const int k = kt + tx;
        if (n < NP && k < KP) {
            const float v = t[tx][ty + i * 8];
            const __nv_bfloat16 h = bhi(v);
            Thi[(size_t)n * KP + k] = h;
            Tlo[(size_t)n * KP + k] = bhi(v - __bfloat162float(h));
        }
    }
}

// ---------------------------------------------------------------------------
// Kernel B: gather + first-order + FM second-order + X hi/lo materialization
// ---------------------------------------------------------------------------
__global__ __launch_bounds__(256) void gather_fm_kernel(
    const int*   __restrict__ feats,
    const float* __restrict__ values,
    const float* __restrict__ weights,
    const float* __restrict__ embedding,
    const float* __restrict__ bias)
{
    const int b   = blockIdx.x;
    const int tid = threadIdx.x;
    const int base = b * NF_;

    __shared__ float s1s[KE_];
    __shared__ float s2s[KE_];
    __shared__ float fsum;

    if (tid < KE_) { s1s[tid] = 0.f; s2s[tid] = 0.f; }
    if (tid == KE_) fsum = 0.f;
    __syncthreads();

    float a1 = 0.f, a2 = 0.f, fw = 0.f;
    const int myk = tid & 15;

    for (int i = tid; i < D_; i += 256) {
        const int f = i >> 4;
        const int feat = feats[base + f];
        const float v = values[base + f];
        const float e = embedding[(size_t)feat * KE_ + (i & 15)];
        const __nv_bfloat16 h = bhi(e);
        g_Xhi[(size_t)b * KP1 + i] = h;
        g_Xlo[(size_t)b * KP1 + i] = bhi(e - __bfloat162float(h));
        const float ev = e * v;
        a1 += ev;
        a2 += ev * ev;
        if ((i & 15) == 0) fw += weights[feat] * v;
    }
    if (tid < KP1 - D_) {   // zero K padding
        g_Xhi[(size_t)b * KP1 + D_ + tid] = __float2bfloat16(0.f);
        g_Xlo[(size_t)b * KP1 + D_ + tid] = __float2bfloat16(0.f);
    }
    atomicAdd(&s1s[myk], a1);
    atomicAdd(&s2s[myk], a2);
    if ((tid & 15) == 0) atomicAdd(&fsum, fw);
    __syncthreads();

    if (tid == 0) {
        float sec = 0.f;
        #pragma unroll
        for (int k = 0; k < KE_; k++) sec += s1s[k] * s1s[k] - s2s[k];
        g_ZP[b] = fsum + bias[0] + 0.5f * sec;
    }
}

// ---------------------------------------------------------------------------
// Kernel C: split-bf16 tensor GEMM via mma.sync.m16n8k16 + ldmatrix + cp.async.
// D[M,N] = A @ B^T, A[M,KP] K-major, B[NP,KP] K-major; both hi/lo bf16.
// CTA 128x64, BK=32, 8 warps (4M x 2N), warp tile 32x32, double-buffered.
// mode 0: out = relu(D+bias) -> bf16 hi/lo at stride KP2, cols>=400 zeroed
// mode 1: out = relu(D+bias) -> fp32 at stride 400, cols>=400 skipped
// ---------------------------------------------------------------------------
#define ASTR 40                 // smem row stride (bf16 units)
#define OFF_AH 0
#define OFF_AL 10240            // bytes
#define OFF_BH 20480
#define OFF_BL 25600
#define STAGE_BYTES 30720
#define SMEM_BYTES (2 * STAGE_BYTES)

__global__ __launch_bounds__(256) void gemm_mma(
    const __nv_bfloat16* __restrict__ Ahi, const __nv_bfloat16* __restrict__ Alo,
    const __nv_bfloat16* __restrict__ Bh,  const __nv_bfloat16* __restrict__ Bl,
    const float* __restrict__ biasp,
    int KP, int nchunks, int mode,
    float* __restrict__ outF,
    __nv_bfloat16* __restrict__ outHi, __nv_bfloat16* __restrict__ outLo)
{
    extern __shared__ char smem[];
    const uint32_t sbase = smem_u32(smem);

    const int tid  = threadIdx.x;
    const int lane = tid & 31;
    const int w    = tid >> 5;
    const int wm   = (w >> 1) << 5;   // warp M offset (0,32,64,96)
    const int wn   = (w & 1) << 5;    // warp N offset (0,32)
    const int grp  = lane >> 2;
    const int thg  = lane & 3;
    const int row0 = blockIdx.y * TM;
    const int col0 = blockIdx.x * TN;

    const int sub = lane >> 3;        // ldmatrix sub-tile select
    const int l8  = lane & 7;

    float acc[2][4][4];
    #pragma unroll
    for (int i = 0; i < 2; i++)
        #pragma unroll
        for (int j = 0; j < 4; j++)
            #pragma unroll
            for (int q = 0; q < 4; q++) acc[i][j][q] = 0.f;

    // ---- async load of one K-chunk into stage s
    auto load_chunk = [&](int c, int s) {
        const int k0 = c * BKC;
        const uint32_t stb = sbase + s * STAGE_BYTES;
        #pragma unroll
        for (int i = 0; i < 2; i++) {
            const int v  = tid + (i << 8);
            const int r  = v >> 2;
            const int c8 = (v & 3) << 3;
            const uint32_t so = (uint32_t)(r * ASTR + c8) * 2;
            const size_t g = (size_t)(row0 + r) * KP + k0 + c8;
            CP16(stb + OFF_AH + so, Ahi + g);
            CP16(stb + OFF_AL + so, Alo + g);
        }
        {
            const int r  = tid >> 2;
            const int c8 = (tid & 3) << 3;
            const uint32_t so = (uint32_t)(r * ASTR + c8) * 2;
            const size_t g = (size_t)(col0 + r) * KP + k0 + c8;
            CP16(stb + OFF_BH + so, Bh + g);
            CP16(stb + OFF_BL + so, Bl + g);
        }
        CP_COMMIT();
    };

    load_chunk(0, 0);

    for (int c = 0; c < nchunks; c++) {
        const int s = c & 1;
        if (c + 1 < nchunks) { load_chunk(c + 1, s ^ 1); CP_WAIT(1); }
        else                 { CP_WAIT(0); }
        __syncthreads();

        const uint32_t stb = sbase + s * STAGE_BYTES;
        #pragma unroll
        for (int kk = 0; kk < BKC; kk += 16) {
            uint32_t ah[2][4], al[2][4], bh[2][4], bl[2][4];
            #pragma unroll
            for (int i = 0; i < 2; i++) {
                const int row = wm + i * 16 + ((sub & 1) << 3) + l8;
                const int kc  = kk + ((sub >> 1) << 3);
                const uint32_t ad = stb + OFF_AH + (uint32_t)(row * ASTR + kc) * 2;
                LDSM4(ah[i], ad);
                LDSM4(al[i], ad + (OFF_AL - OFF_AH));
            }
            #pragma unroll
            for (int jj = 0; jj < 2; jj++) {
                const int row = wn + jj * 16 + ((sub >> 1) << 3) + l8;
                const int kc  = kk + ((sub & 1) << 3);
                const uint32_t bd = stb + OFF_BH + (uint32_t)(row * ASTR + kc) * 2;
                LDSM4(bh[jj], bd);
                LDSM4(bl[jj], bd + (OFF_BL - OFF_BH));
            }
            #pragma unroll
            for (int i = 0; i < 2; i++)
                #pragma unroll
                for (int j = 0; j < 4; j++) {
                    const uint32_t b0h = bh[j >> 1][(j & 1) * 2];
                    const uint32_t b1h = bh[j >> 1][(j & 1) * 2 + 1];
                    const uint32_t b0l = bl[j >> 1][(j & 1) * 2];
                    const uint32_t b1l = bl[j >> 1][(j & 1) * 2 + 1];
                    mma16(acc[i][j], ah[i], b0h, b1h);
                    mma16(acc[i][j], ah[i], b0l, b1l);
                    mma16(acc[i][j], al[i], b0h, b1h);
                }
        }
        __syncthreads();
    }

    // ---- epilogue: bias + relu, write straight from registers
    const float bv = *biasp;
    #pragma unroll
    for (int i = 0; i < 2; i++) {
        #pragma unroll
        for (int j = 0; j < 4; j++) {
            const int r = row0 + wm + i * 16 + grp;
            const int cc = col0 + wn + j * 8 + (thg << 1);
            #pragma unroll
            for (int half = 0; half < 2; half++) {
                const int rr = r + half * 8;
                const float x0r = fmaxf(acc[i][j][half * 2]     + bv, 0.f);
                const float x1r = fmaxf(acc[i][j][half * 2 + 1] + bv, 0.f);
                if (mode == 0) {
                    const float x0 = (cc     < H_) ? x0r : 0.f;
                    const float x1 = (cc + 1 < H_) ? x1r : 0.f;
                    const __nv_bfloat16 h0 = bhi(x0), h1 = bhi(x1);
                    __nv_bfloat162 hp, lp;
                    hp.x = h0; hp.y = h1;
                    lp.x = bhi(x0 - __bfloat162float(h0));
                    lp.y = bhi(x1 - __bfloat162float(h1));
                    const size_t o = (size_t)rr * KP2 + cc;
                    *reinterpret_cast<__nv_bfloat162*>(outHi + o) = hp;
                    *reinterpret_cast<__nv_bfloat162*>(outLo + o) = lp;
                } else {
                    if (cc < H_) {
                        float2 q; q.x = x0r; q.y = x1r;
                        *reinterpret_cast<float2*>(outF + (size_t)rr * H_ + cc) = q;
                    }
                }
            }
        }
    }
}

// ---------------------------------------------------------------------------
// Kernel D: per-sample GEMV + relu + FM partial + sigmoid
// ---------------------------------------------------------------------------
__global__ __launch_bounds__(256) void final_kernel(
    const float* __restrict__ W2,
    const float* __restrict__ b2,
    float*       __restrict__ out)
{
    const int gw   = (blockIdx.x * blockDim.x + threadIdx.x) >> 5;
    const int lane = threadIdx.x & 31;
    if (gw >= B_) return;

    float s = 0.f;
    const float* h = &g_H1[(size_t)gw * H_];
    for (int j = lane * 4; j < H_; j += 128) {
        const float4 hv = *reinterpret_cast<const float4*>(&h[j]);
        const float4 wv = *reinterpret_cast<const float4*>(&W2[j]);
        s += hv.x * wv.x + hv.y * wv.y + hv.z * wv.z + hv.w * wv.w;
    }
    #pragma unroll
    for (int o = 16; o; o >>= 1) s += __shfl_xor_sync(0xffffffffu, s, o);

    if (lane == 0) {
        const float hi = fmaxf(s + b2[0], 0.f);
        const float z  = g_ZP[gw] + hi;
        out[gw] = 1.f / (1.f + expf(-z));
    }
}

// ---------------------------------------------------------------------------
extern "C" void kernel_launch(void* const* d_in, const int* in_sizes, int n_in,
                              void* d_out, int out_size)
{
    const int*   feats   = (const int*)  d_in[1];
    const float* values  = (const float*)d_in[2];
    const float* bias    = (const float*)d_in[3];
    const float* weights = (const float*)d_in[4];
    const float* emb     = (const float*)d_in[5];
    const float* W0      = (const float*)d_in[6];
    const float* b0      = (const float*)d_in[7];
    const float* W1      = (const float*)d_in[8];
    const float* b1      = (const float*)d_in[9];
    const float* W2      = (const float*)d_in[10];
    const float* b2      = (const float*)d_in[11];
    float* out = (float*)d_out;

    __nv_bfloat16 *Xhi, *Xlo, *W0hi, *W0lo, *W1hi, *W1lo, *H0hi, *H0lo;
    float *H1;
    cudaGetSymbolAddress((void**)&Xhi,  g_Xhi);
    cudaGetSymbolAddress((void**)&Xlo,  g_Xlo);
    cudaGetSymbolAddress((void**)&W0hi, g_W0hi);
    cudaGetSymbolAddress((void**)&W0lo, g_W0lo);
    cudaGetSymbolAddress((void**)&W1hi, g_W1hi);
    cudaGetSymbolAddress((void**)&W1lo, g_W1lo);
    cudaGetSymbolAddress((void**)&H0hi, g_H0hi);
    cudaGetSymbolAddress((void**)&H0lo, g_H0lo);
    cudaGetSymbolAddress((void**)&H1,   g_H1);

    static int smem_set = 0;
    if (!smem_set) {
        cudaFuncSetAttribute(gemm_mma, cudaFuncAttributeMaxDynamicSharedMemorySize,
                             SMEM_BYTES);
        smem_set = 1;
    }

    // 0) weight transpose + bf16 split (zero-padded to [448][KP])
    {
        dim3 g1((KP1 + 31) / 32, NP_ / 32);
        transpose_split<<<g1, 256>>>(W0, W0hi, W0lo, D_, H_, KP1, NP_);
        dim3 g2((KP2 + 31) / 32, NP_ / 32);
        transpose_split<<<g2, 256>>>(W1, W1hi, W1lo, H_, H_, KP2, NP_);
    }
    // 1) gather + FM + X hi/lo
    gather_fm_kernel<<<B_, 256>>>(feats, values, weights, emb, bias);

    // 2) H0 = relu(X @ W0 + b0) -> bf16 hi/lo [16384][448] (pad cols zeroed)
    {
        dim3 grid(NP_ / TN, B_ / TM);
        gemm_mma<<<grid, 256, SMEM_BYTES>>>(Xhi, Xlo, W0hi, W0lo, b0,
                                            KP1, KP1 / BKC, 0,
                                            nullptr, H0hi, H0lo);
    }
    // 3) H1 = relu(H0 @ W1 + b1) -> fp32 [16384][400]
    {
        dim3 grid(NP_ / TN, B_ / TM);
        gemm_mma<<<grid, 256, SMEM_BYTES>>>(H0hi, H0lo, W1hi, W1lo, b1,
                                            KP2, KP2 / BKC, 1,
                                            H1, nullptr, nullptr);
    }
    // 4) out = sigmoid(ZP + relu(H1 @ W2 + b2))
    {
        const int wpb = 8;
        final_kernel<<<(B_ + wpb - 1) / wpb, wpb * 32>>>(W2, b2, out);
    }
}